// round 14
// baseline (speedup 1.0000x reference)
#include <cuda_runtime.h>
#include <math.h>

#define BB 64
#define TT 256
#define FF 64
#define UU 512
#define GG 2048      // 4*UU
#define NBLK 128
#define NTHR 512
#define CU 4         // units per block
#define NC 16        // gate-columns per block
#define NW 16        // warps (k split 16 ways)
#define KW 32        // k per warp
#define K8 8         // k per cp.async group
#define NG 4         // groups per warp (KW/K8)
#define HR 68        // staged h row stride (floats)
#define FPAD 32      // flag padding (128B line each)

// ---- static device scratch (no cudaMalloc anywhere) ----
__device__ __align__(256) float g_hsT[(size_t)TT * UU * BB]; // h: [(t*512+u)*64+b]
__device__ __align__(256) float g_xzT[(size_t)TT * GG * BB]; // xz+bias: [t][g][b]
__device__ float g_coef[TT];
__device__ float g_shift[TT];
__device__ float g_sumW;
__device__ unsigned g_flags[NBLK * FPAD];     // per-block step flags, reset by prep

__device__ __forceinline__ float sigmoidf_(float x) { return 1.f / (1.f + expf(-x)); }

// packed fp32x2 FMA (Blackwell)
__device__ __forceinline__ unsigned long long fma2(unsigned long long a,
                                                   unsigned long long b,
                                                   unsigned long long c) {
    unsigned long long d;
    asm("fma.rn.f32x2 %0, %1, %2, %3;" : "=l"(d) : "l"(a), "l"(b), "l"(c));
    return d;
}
__device__ __forceinline__ unsigned long long pack2(float v) {
    unsigned long long p;
    unsigned u = __float_as_uint(v);
    asm("mov.b64 %0, {%1, %1};" : "=l"(p) : "r"(u));
    return p;
}
__device__ __forceinline__ unsigned ld_acq_gpu(const unsigned* p) {
    unsigned v;
    asm volatile("ld.acquire.gpu.global.u32 %0, [%1];" : "=r"(v) : "l"(p) : "memory");
    return v;
}
__device__ __forceinline__ void st_rel_gpu(unsigned* p, unsigned v) {
    asm volatile("st.release.gpu.global.u32 [%0], %1;" :: "l"(p), "r"(v) : "memory");
}
__device__ __forceinline__ void cp_async16(float* smem_dst, const void* gmem_src) {
    unsigned s = (unsigned)__cvta_generic_to_shared(smem_dst);
    asm volatile("cp.async.cg.shared.global [%0], [%1], 16;\n" :: "r"(s), "l"(gmem_src));
}
#define CP_COMMIT() asm volatile("cp.async.commit_group;" ::: "memory")
#define CP_WAIT_1() asm volatile("cp.async.wait_group 1;" ::: "memory")
#define CP_WAIT_0() asm volatile("cp.async.wait_group 0;" ::: "memory")

// one no-op pad so ncu's capture slot still lands on lstm_persist
__global__ void pad_kernel() {}

// ---------------------------------------------------------------------------
// prep: coef/shift/sumW; block TT also resets the per-block flags.
// ---------------------------------------------------------------------------
__global__ void prep_kernel(const float* __restrict__ attW,
                            const float* __restrict__ attb,
                            const float* __restrict__ outW)
{
    __shared__ float red[256];
    int tid = threadIdx.x;
    if (blockIdx.x < TT) {
        int t = blockIdx.x;
        float s = 0.f;
        for (int j = tid; j < t; j += 256) s += attW[t * TT + j];
        red[tid] = s;
        __syncthreads();
        for (int off = 128; off > 0; off >>= 1) {
            if (tid < off) red[tid] += red[tid + off];
            __syncthreads();
        }
        if (tid == 0) {
            g_coef[t]  = (t == 0) ? 1.f : red[0];
            g_shift[t] = (t == 0) ? 0.f : attb[t];
        }
    } else {
        if (tid < NBLK) g_flags[tid * FPAD] = 0u;
        red[tid] = outW[tid] + outW[tid + 256];
        __syncthreads();
        for (int off = 128; off > 0; off >>= 1) {
            if (tid < off) red[tid] += red[tid + off];
            __syncthreads();
        }
        if (tid == 0) g_sumW = red[0];
    }
}

// ---------------------------------------------------------------------------
// xz precompute: xzT[t][g][b] = bias[g] + sum_f x[b][t][f] * Wk[f][g]
// ---------------------------------------------------------------------------
__global__ void xz_kernel(const float* __restrict__ x,
                          const float* __restrict__ Wk,
                          const float* __restrict__ bias)
{
    __shared__ float sx[64 * 65];     // x_t [b][f], padded
    __shared__ float sout[256 * 17];  // [g][16 b], padded

    const int t   = blockIdx.y;
    const int g0  = blockIdx.x * 256;
    const int tid = threadIdx.x;
    const int g   = g0 + tid;

    for (int i = tid; i < 64 * 16; i += 256) {
        int b  = i >> 4;
        int f4 = (i & 15) << 2;
        float4 v = *(const float4*)(x + ((size_t)b * TT + t) * FF + f4);
        sx[b * 65 + f4 + 0] = v.x;
        sx[b * 65 + f4 + 1] = v.y;
        sx[b * 65 + f4 + 2] = v.z;
        sx[b * 65 + f4 + 3] = v.w;
    }

    float wreg[64];
    #pragma unroll 16
    for (int f = 0; f < 64; ++f) wreg[f] = Wk[(size_t)f * GG + g];
    const float bv = bias[g];
    __syncthreads();

    for (int bc = 0; bc < 4; ++bc) {
        float acc[16];
        #pragma unroll
        for (int bb = 0; bb < 16; ++bb) acc[bb] = bv;
        #pragma unroll 8
        for (int f = 0; f < 64; ++f) {
            float w = wreg[f];
            const float* sxb = sx + (bc * 16) * 65 + f;
            #pragma unroll
            for (int bb = 0; bb < 16; ++bb)
                acc[bb] += sxb[bb * 65] * w;
        }
        __syncthreads();
        #pragma unroll
        for (int bb = 0; bb < 16; ++bb) sout[tid * 17 + bb] = acc[bb];
        __syncthreads();
        #pragma unroll
        for (int r = 0; r < 4; ++r) {
            int idx = r * 256 + tid;
            int gg = idx >> 2, s4 = (idx & 3) << 2;
            float4 v = make_float4(sout[gg * 17 + s4 + 0], sout[gg * 17 + s4 + 1],
                                   sout[gg * 17 + s4 + 2], sout[gg * 17 + s4 + 3]);
            *(float4*)(g_xzT + ((size_t)t * GG + g0 + gg) * BB + bc * 16 + s4) = v;
        }
    }
}

// ---------------------------------------------------------------------------
// Persistent LSTM with WAVE-PIPELINED dependencies (no global barrier).
// 128 blocks, 512 threads (16 warps, k split 16x).
// Warp wid consumes h-units [32*wid, 32*wid+32) -> produced by exactly the
// 8 blocks [8*wid, 8*wid+8). Each warp waits ONLY on those 8 flags (each
// lane has its own acquire), then runs its cp.async + GEMM. The only block
// convergence is the sg reduction; inter-block skew becomes a pipeline wave
// instead of a per-step global max.
// ---------------------------------------------------------------------------
// smem (floats):
//   w4  [512][16]      =  8192 (32 KB)
//   sg  [16][16][68]   = 17408 (68 KB)
//   sg2 [16][68]       =  1088 (4.25 KB)
//   hst [16][2][8][68] = 17408 (68 KB)
#define OFF_W4   0
#define OFF_SG   (UU * NC)
#define OFF_SG2  (OFF_SG + NW * NC * 68)
#define OFF_HST  (OFF_SG2 + NC * 68)
#define SMEM_FLOATS (OFF_HST + NW * 2 * K8 * HR)

__global__ void __launch_bounds__(NTHR, 1)
lstm_persist(const float* __restrict__ Rk)    // (U,4U)
{
    extern __shared__ float smem[];
    float* w4  = smem + OFF_W4;
    float* sg  = smem + OFF_SG;
    float* sg2 = smem + OFF_SG2;
    float* hst = smem + OFF_HST;

    const int tid = threadIdx.x;
    const int bid = blockIdx.x;
    const int u0  = bid * CU;

    // ---- one-time weight staging (quad-packed scalar) ----
    for (int idx = tid; idx < UU * NC; idx += NTHR) {
        int k = idx >> 4, m = idx & 15;
        int c = (m >> 2) + ((m & 3) << 2);          // col for slot m
        int gcol = (c >> 2) * UU + u0 + (c & 3);
        w4[k * 16 + m] = Rk[(size_t)k * GG + gcol];
    }

    // GEMM identity
    const int wid  = tid >> 5;        // warp 0..15 -> k range [wid*32, ..)
    const int lane = tid & 31;
    const int cq   = lane >> 3;       // 0..3: cols {cq, cq+4, cq+8, cq+12}
    const int bo   = lane & 7;        // 0..7: batches [bo*8, bo*8+8)
    const int kb   = wid * KW;
    const int b0   = bo * 8;

    // producer flag this lane polls: blocks [8*wid, 8*wid+8)
    const unsigned* myflag = &g_flags[(8 * wid + (lane & 7)) * FPAD];

    // cp.async lane mapping
    const int cpk8 = lane >> 4;       // 0/1
    const int cpb4 = (lane & 15) << 2;
    float* slab = hst + (size_t)wid * (2 * K8 * HR);

    // stage-1 reduction identity
    const int rc = tid & 15;
    const int rb = (tid >> 4) * 2;

    // pointwise identity: unit pj, batch pb
    const int pj = (tid >> 6) & 3;
    const int pb = tid & 63;
    float creg = 0.f;

    // xz pointers (bias folded in)
    const float* xp0 = g_xzT + ((size_t)(0 * UU + u0 + pj)) * BB + pb;
    const float* xp1 = g_xzT + ((size_t)(1 * UU + u0 + pj)) * BB + pb;
    const float* xp2 = g_xzT + ((size_t)(2 * UU + u0 + pj)) * BB + pb;
    const float* xp3 = g_xzT + ((size_t)(3 * UU + u0 + pj)) * BB + pb;

    const float4* wp = (const float4*)w4 + (size_t)kb * 4 + cq;

    __syncthreads();

    for (int t = 0; t < TT; ++t) {
        // ---- prefetch this step's xz (independent of any wait) ----
        float xz0 = __ldg(xp0), xz1 = __ldg(xp1);
        float xz2 = __ldg(xp2), xz3 = __ldg(xp3);
        xp0 += (size_t)GG * BB; xp1 += (size_t)GG * BB;
        xp2 += (size_t)GG * BB; xp3 += (size_t)GG * BB;

        // accumulators: [col j][batch pair p]
        unsigned long long a[4][4];
        #pragma unroll
        for (int j = 0; j < 4; ++j)
            #pragma unroll
            for (int p = 0; p < 4; ++p) a[j][p] = 0ull;

        if (t > 0) {
            // ---- per-warp wait: only this warp's 8 producer blocks ----
            while (ld_acq_gpu(myflag) < (unsigned)t) { }
            __syncwarp();

            const float* hsrc = g_hsT + ((size_t)(t - 1) * UU + kb) * BB;

            // group 0
            #pragma unroll
            for (int r = 0; r < 4; ++r) {
                int k8 = r * 2 + cpk8;
                cp_async16(slab + k8 * HR + cpb4, hsrc + k8 * 64 + cpb4);
            }
            CP_COMMIT();

            // ---- 4 groups of 8 k, cp.async pipelined ----
            #pragma unroll
            for (int g = 0; g < NG; ++g) {
                if (g + 1 < NG) {
                    float* dbuf = slab + ((g + 1) & 1) * (K8 * HR);
                    const float* src = hsrc + (size_t)((g + 1) * K8) * 64;
                    #pragma unroll
                    for (int r = 0; r < 4; ++r) {
                        int k8 = r * 2 + cpk8;
                        cp_async16(dbuf + k8 * HR + cpb4, src + k8 * 64 + cpb4);
                    }
                    CP_COMMIT();
                    CP_WAIT_1();
                } else {
                    CP_WAIT_0();
                }
                __syncwarp();

                const float* cbuf = slab + (g & 1) * (K8 * HR) + b0;
                #pragma unroll
                for (int k8 = 0; k8 < K8; ++k8) {
                    float4 wq = wp[(size_t)(g * K8 + k8) * 4];
                    ulonglong2 ca = *(const ulonglong2*)(cbuf + k8 * HR);
                    ulonglong2 cb = *(const ulonglong2*)(cbuf + k8 * HR + 4);
                    unsigned long long w0 = pack2(wq.x);
                    unsigned long long w1 = pack2(wq.y);
                    unsigned long long w2 = pack2(wq.z);
                    unsigned long long w3 = pack2(wq.w);
                    a[0][0] = fma2(ca.x, w0, a[0][0]); a[0][1] = fma2(ca.y, w0, a[0][1]);
                    a[0][2] = fma2(cb.x, w0, a[0][2]); a[0][3] = fma2(cb.y, w0, a[0][3]);
                    a[1][0] = fma2(ca.x, w1, a[1][0]); a[1][1] = fma2(ca.y, w1, a[1][1]);
                    a[1][2] = fma2(cb.x, w1, a[1][2]); a[1][3] = fma2(cb.y, w1, a[1][3]);
                    a[2][0] = fma2(ca.x, w2, a[2][0]); a[2][1] = fma2(ca.y, w2, a[2][1]);
                    a[2][2] = fma2(cb.x, w2, a[2][2]); a[2][3] = fma2(cb.y, w2, a[2][3]);
                    a[3][0] = fma2(ca.x, w3, a[3][0]); a[3][1] = fma2(ca.y, w3, a[3][1]);
                    a[3][2] = fma2(cb.x, w3, a[3][2]); a[3][3] = fma2(cb.y, w3, a[3][3]);
                }
                __syncwarp();
            }
        }

        // ---- write partials: sg[wid][c][b] ----
        #pragma unroll
        for (int j = 0; j < 4; ++j) {
            int c = cq + 4 * j;
            float* dst = sg + (size_t)(wid * NC + c) * 68 + b0;
            *(ulonglong2*)(dst)     = make_ulonglong2(a[j][0], a[j][1]);
            *(ulonglong2*)(dst + 4) = make_ulonglong2(a[j][2], a[j][3]);
        }
        __syncthreads();   // ONLY block-wide convergence point

        // ---- stage 1: sum 16 k-partials ----
        {
            float2 s = make_float2(0.f, 0.f);
            #pragma unroll
            for (int w = 0; w < NW; ++w) {
                float2 v = *(const float2*)(sg + (size_t)(w * NC + rc) * 68 + rb);
                s.x += v.x; s.y += v.y;
            }
            *(float2*)(sg2 + rc * 68 + rb) = s;
        }
        __syncthreads();

        // ---- stage 2 pointwise (tid < 256): gates + state update ----
        if (tid < 256) {
            float iv = xz0 + sg2[(0 * 4 + pj) * 68 + pb];
            float fv = xz1 + sg2[(1 * 4 + pj) * 68 + pb];
            float gv = xz2 + sg2[(2 * 4 + pj) * 68 + pb];
            float ov = xz3 + sg2[(3 * 4 + pj) * 68 + pb];
            creg = sigmoidf_(fv) * creg + sigmoidf_(iv) * tanhf(gv);
            float hval = sigmoidf_(ov) * tanhf(creg);
            g_hsT[((size_t)t * UU + u0 + pj) * 64 + pb] = hval;
        }

        // ---- arrive: release h(t) via own flag (h stores hb-before via bar) ----
        if (t + 1 < TT) {
            __syncthreads();
            if (tid == 0) st_rel_gpu(&g_flags[bid * FPAD], (unsigned)(t + 1));
        }
    }
}

// ---------------------------------------------------------------------------
__global__ void out_kernel(const float* __restrict__ outW,
                           const float* __restrict__ outb,
                           float* __restrict__ y)
{
    int t  = blockIdx.x;
    int b  = threadIdx.x & 63;
    int ug = threadIdx.x >> 6;   // 0..3
    float s = 0.f;
    const float* base = g_hsT + (size_t)t * UU * BB;
    #pragma unroll 4
    for (int u = ug * 128; u < ug * 128 + 128; ++u)
        s += base[(size_t)u * 64 + b] * outW[u];
    __shared__ float red[4][64];
    red[ug][b] = s;
    __syncthreads();
    if (ug == 0) {
        float v = red[0][b] + red[1][b] + red[2][b] + red[3][b];
        v = g_coef[t] * v + g_shift[t] * g_sumW + outb[0];
        y[b * TT + t] = 1.f / (1.f + expf(-v));
    }
}

// ---------------------------------------------------------------------------
extern "C" void kernel_launch(void* const* d_in, const int* in_sizes, int n_in,
                              void* d_out, int out_size)
{
    (void)in_sizes; (void)n_in; (void)out_size;
    const float* inputs = (const float*)d_in[0];
    const float* kernel = (const float*)d_in[1];
    const float* rec    = (const float*)d_in[2];
    const float* bias   = (const float*)d_in[3];
    const float* attW   = (const float*)d_in[4];
    const float* attb   = (const float*)d_in[5];
    const float* outW   = (const float*)d_in[6];
    const float* outb   = (const float*)d_in[7];
    float* y = (float*)d_out;

    static int smem_set = 0;
    size_t smem_bytes = SMEM_FLOATS * sizeof(float);   // ~173 KB
    if (!smem_set) {
        cudaFuncSetAttribute(lstm_persist,
                             cudaFuncAttributeMaxDynamicSharedMemorySize,
                             (int)smem_bytes);
        smem_set = 1;
    }

    pad_kernel<<<1, 32>>>();                           // keep persist at ncu slot 5
    prep_kernel<<<TT + 1, 256>>>(attW, attb, outW);    // also resets flags
    xz_kernel<<<dim3(GG / 256, TT), 256>>>(inputs, kernel, bias);
    lstm_persist<<<NBLK, NTHR, smem_bytes>>>(rec);
    out_kernel<<<TT, 256>>>(outW, outb, y);
}

// round 16
// speedup vs baseline: 1.4771x; 1.4771x over previous
#include <cuda_runtime.h>
#include <math.h>

#define BB 64
#define TT 256
#define FF 64
#define UU 512
#define GG 2048      // 4*UU
#define NBLK 128
#define NTHR 512
#define CUU 8        // units per block
#define NCC 32       // gate-columns per block (4 gates x 8 units)
#define BBH 32       // batches per block
#define NW 16        // warps (k split 16 ways)
#define KW 32        // k per warp
#define K8 8         // k per cp.async group
#define NG 4         // groups per warp
#define HRW 36       // staged h row stride (floats, 16B-aligned)
#define SGR 36       // sg row stride (floats, 16B-aligned)
#define SG2R 34      // sg2 row stride (floats, 8B-aligned)
#define FPAD 32      // flag padding (128B line each)

// ---- static device scratch (no cudaMalloc anywhere) ----
__device__ __align__(256) float g_hsT[(size_t)TT * UU * BB]; // h: [(t*512+u)*64+b]
__device__ __align__(256) float g_xzT[(size_t)TT * GG * BB]; // xz+bias: [t][g][b]
__device__ float g_coef[TT];
__device__ float g_shift[TT];
__device__ float g_sumW;
__device__ unsigned g_flags[NBLK * FPAD];     // per-block step flags, reset by prep

__device__ __forceinline__ float sigmoidf_(float x) { return 1.f / (1.f + expf(-x)); }

// packed fp32x2 FMA (Blackwell)
__device__ __forceinline__ unsigned long long fma2(unsigned long long a,
                                                   unsigned long long b,
                                                   unsigned long long c) {
    unsigned long long d;
    asm("fma.rn.f32x2 %0, %1, %2, %3;" : "=l"(d) : "l"(a), "l"(b), "l"(c));
    return d;
}
__device__ __forceinline__ unsigned long long pack2(float v) {
    unsigned long long p;
    unsigned u = __float_as_uint(v);
    asm("mov.b64 %0, {%1, %1};" : "=l"(p) : "r"(u));
    return p;
}
__device__ __forceinline__ unsigned ld_acq_gpu(const unsigned* p) {
    unsigned v;
    asm volatile("ld.acquire.gpu.global.u32 %0, [%1];" : "=r"(v) : "l"(p) : "memory");
    return v;
}
__device__ __forceinline__ void st_rel_gpu(unsigned* p, unsigned v) {
    asm volatile("st.release.gpu.global.u32 [%0], %1;" :: "l"(p), "r"(v) : "memory");
}
__device__ __forceinline__ void cp_async16(float* smem_dst, const void* gmem_src) {
    unsigned s = (unsigned)__cvta_generic_to_shared(smem_dst);
    asm volatile("cp.async.cg.shared.global [%0], [%1], 16;\n" :: "r"(s), "l"(gmem_src));
}
#define CP_COMMIT() asm volatile("cp.async.commit_group;" ::: "memory")
#define CP_WAIT_1() asm volatile("cp.async.wait_group 1;" ::: "memory")
#define CP_WAIT_0() asm volatile("cp.async.wait_group 0;" ::: "memory")

// one no-op pad so ncu's capture slot still lands on lstm_persist
__global__ void pad_kernel() {}

// ---------------------------------------------------------------------------
__global__ void prep_kernel(const float* __restrict__ attW,
                            const float* __restrict__ attb,
                            const float* __restrict__ outW)
{
    __shared__ float red[256];
    int tid = threadIdx.x;
    if (blockIdx.x < TT) {
        int t = blockIdx.x;
        float s = 0.f;
        for (int j = tid; j < t; j += 256) s += attW[t * TT + j];
        red[tid] = s;
        __syncthreads();
        for (int off = 128; off > 0; off >>= 1) {
            if (tid < off) red[tid] += red[tid + off];
            __syncthreads();
        }
        if (tid == 0) {
            g_coef[t]  = (t == 0) ? 1.f : red[0];
            g_shift[t] = (t == 0) ? 0.f : attb[t];
        }
    } else {
        if (tid < NBLK) g_flags[tid * FPAD] = 0u;
        red[tid] = outW[tid] + outW[tid + 256];
        __syncthreads();
        for (int off = 128; off > 0; off >>= 1) {
            if (tid < off) red[tid] += red[tid + off];
            __syncthreads();
        }
        if (tid == 0) g_sumW = red[0];
    }
}

// ---------------------------------------------------------------------------
// xz precompute: xzT[t][g][b] = bias[g] + sum_f x[b][t][f] * Wk[f][g]
// ---------------------------------------------------------------------------
__global__ void xz_kernel(const float* __restrict__ x,
                          const float* __restrict__ Wk,
                          const float* __restrict__ bias)
{
    __shared__ float sx[64 * 65];
    __shared__ float sout[256 * 17];

    const int t   = blockIdx.y;
    const int g0  = blockIdx.x * 256;
    const int tid = threadIdx.x;
    const int g   = g0 + tid;

    for (int i = tid; i < 64 * 16; i += 256) {
        int b  = i >> 4;
        int f4 = (i & 15) << 2;
        float4 v = *(const float4*)(x + ((size_t)b * TT + t) * FF + f4);
        sx[b * 65 + f4 + 0] = v.x;
        sx[b * 65 + f4 + 1] = v.y;
        sx[b * 65 + f4 + 2] = v.z;
        sx[b * 65 + f4 + 3] = v.w;
    }

    float wreg[64];
    #pragma unroll 16
    for (int f = 0; f < 64; ++f) wreg[f] = Wk[(size_t)f * GG + g];
    const float bv = bias[g];
    __syncthreads();

    for (int bc = 0; bc < 4; ++bc) {
        float acc[16];
        #pragma unroll
        for (int bb = 0; bb < 16; ++bb) acc[bb] = bv;
        #pragma unroll 8
        for (int f = 0; f < 64; ++f) {
            float w = wreg[f];
            const float* sxb = sx + (bc * 16) * 65 + f;
            #pragma unroll
            for (int bb = 0; bb < 16; ++bb)
                acc[bb] += sxb[bb * 65] * w;
        }
        __syncthreads();
        #pragma unroll
        for (int bb = 0; bb < 16; ++bb) sout[tid * 17 + bb] = acc[bb];
        __syncthreads();
        #pragma unroll
        for (int r = 0; r < 4; ++r) {
            int idx = r * 256 + tid;
            int gg = idx >> 2, s4 = (idx & 3) << 2;
            float4 v = make_float4(sout[gg * 17 + s4 + 0], sout[gg * 17 + s4 + 1],
                                   sout[gg * 17 + s4 + 2], sout[gg * 17 + s4 + 3]);
            *(float4*)(g_xzT + ((size_t)t * GG + g0 + gg) * BB + bc * 16 + s4) = v;
        }
    }
}

// ---------------------------------------------------------------------------
// Persistent LSTM, re-tiled for 2x less h fan-out.
// 128 blocks = 64 unit-groups (8 units) x 2 batch-halves (32 batches).
// Block reads only its 32-batch half of h(t-1): 64 KB -> chip 8 MB/step.
// 512 threads, 16 warps, k split 16x; warp: 32 cols x 32 b for its 32 k;
// thread: 4 cols x 8 batches = 16 f32x2 accumulators.
// w quad-packed (slot m = cq*4+j <-> col cq+8j): 1 LDS.128 per k per thread.
// h via per-warp cp.async double-buffered slab (per group: 8 k x 32 floats
// = 64 chunks of 16B = 2 rounds x 32 lanes). Flags: tid<128 poll.
// ---------------------------------------------------------------------------
// smem (floats):
//   w4  [512][32]      = 16384 (64 KB)
//   sg  [16][32][36]   = 18432 (72 KB)
//   sg2 [32][34]       =  1088 (4.25 KB)
//   hst [16][2][8][36] =  9216 (36 KB)
#define OFF_W4   0
#define OFF_SG   (UU * NCC)
#define OFF_SG2  (OFF_SG + NW * NCC * SGR)
#define OFF_HST  (OFF_SG2 + NCC * SG2R)
#define SMEM_FLOATS (OFF_HST + NW * 2 * K8 * HRW)

__global__ void __launch_bounds__(NTHR, 1)
lstm_persist(const float* __restrict__ Rk)    // (U,4U)
{
    extern __shared__ float smem[];
    float* w4  = smem + OFF_W4;
    float* sg  = smem + OFF_SG;
    float* sg2 = smem + OFF_SG2;
    float* hst = smem + OFF_HST;

    const int tid = threadIdx.x;
    const int bid = blockIdx.x;
    const int u0  = (bid >> 1) * CUU;      // unit group
    const int bO  = (bid & 1) * BBH;       // batch half offset

    // ---- one-time weight staging: w4[k][m], slot m = cq*4+j <-> col cq+8j ----
    for (int idx = tid; idx < UU * NCC; idx += NTHR) {
        int k = idx >> 5, m = idx & 31;
        int c = (m >> 2) + ((m & 3) << 3);           // col for slot m
        int gcol = (c >> 3) * UU + u0 + (c & 7);
        w4[k * 32 + m] = Rk[(size_t)k * GG + gcol];
    }

    // GEMM identity
    const int wid  = tid >> 5;        // warp 0..15 -> k range [wid*32, ..)
    const int lane = tid & 31;
    const int cq   = lane >> 2;       // 0..7: cols {cq, cq+8, cq+16, cq+24}
    const int bo   = lane & 3;        // 0..3: batches [8bo, 8bo+8) of this half
    const int kb   = wid * KW;
    const int b0   = bo * 8;

    // cp.async lane mapping: per group 8 k x 32 floats = 64 chunks of 16B
    // -> 2 rounds x 32 lanes; flat = r*32 + lane; k8 = flat>>3 (0..7),
    //    c16 = (flat&7)*4 (0..28)
    float* slab = hst + (size_t)wid * (2 * K8 * HRW);

    // stage-1 reduction identity: col rc, batch pair rb
    const int rc = tid & 31;          // 0..31
    const int rb = (tid >> 5) * 2;    // 0,2,...,30

    // pointwise identity (tid < 256): unit pj (0..7), batch pb (0..31)
    const int pj = (tid >> 5) & 7;
    const int pb = tid & 31;
    float creg = 0.f;

    // xz pointers (bias folded in)
    const float* xp0 = g_xzT + ((size_t)(0 * UU + u0 + pj)) * BB + bO + pb;
    const float* xp1 = g_xzT + ((size_t)(1 * UU + u0 + pj)) * BB + bO + pb;
    const float* xp2 = g_xzT + ((size_t)(2 * UU + u0 + pj)) * BB + bO + pb;
    const float* xp3 = g_xzT + ((size_t)(3 * UU + u0 + pj)) * BB + bO + pb;

    const float4* wp = (const float4*)w4 + (size_t)kb * 8;   // [k][8 quads]

    __syncthreads();

    for (int t = 0; t < TT; ++t) {
        // ---- prefetch this step's xz ----
        float xz0 = __ldg(xp0), xz1 = __ldg(xp1);
        float xz2 = __ldg(xp2), xz3 = __ldg(xp3);
        xp0 += (size_t)GG * BB; xp1 += (size_t)GG * BB;
        xp2 += (size_t)GG * BB; xp3 += (size_t)GG * BB;

        // accumulators: [col j][batch pair p]
        unsigned long long a[4][4];
        #pragma unroll
        for (int j = 0; j < 4; ++j)
            #pragma unroll
            for (int p = 0; p < 4; ++p) a[j][p] = 0ull;

        if (t > 0) {
            // ---- wait: every block's flag must reach t ----
            if (tid < NBLK) {
                while (ld_acq_gpu(&g_flags[tid * FPAD]) < (unsigned)t) { }
            }
            __syncthreads();

            // h slice base: this warp's k rows, this block's batch half
            const float* hsrc = g_hsT + ((size_t)(t - 1) * UU + kb) * BB + bO;

            // group 0: 64 chunks = 2 rounds x 32 lanes
            #pragma unroll
            for (int r = 0; r < 2; ++r) {
                int flat = r * 32 + lane;
                int k8   = flat >> 3;
                int c16  = (flat & 7) << 2;
                cp_async16(slab + k8 * HRW + c16, hsrc + (size_t)k8 * BB + c16);
            }
            CP_COMMIT();

            // ---- 4 groups of 8 k, cp.async pipelined ----
            #pragma unroll
            for (int g = 0; g < NG; ++g) {
                if (g + 1 < NG) {
                    float* dbuf = slab + ((g + 1) & 1) * (K8 * HRW);
                    const float* src = hsrc + (size_t)((g + 1) * K8) * BB;
                    #pragma unroll
                    for (int r = 0; r < 2; ++r) {
                        int flat = r * 32 + lane;
                        int k8   = flat >> 3;
                        int c16  = (flat & 7) << 2;
                        cp_async16(dbuf + k8 * HRW + c16, src + (size_t)k8 * BB + c16);
                    }
                    CP_COMMIT();
                    CP_WAIT_1();
                } else {
                    CP_WAIT_0();
                }
                __syncwarp();

                const float* cbuf = slab + (g & 1) * (K8 * HRW) + b0;
                #pragma unroll
                for (int k8 = 0; k8 < K8; ++k8) {
                    float4 wq = wp[(size_t)(g * K8 + k8) * 8 + cq];
                    ulonglong2 ca = *(const ulonglong2*)(cbuf + k8 * HRW);
                    ulonglong2 cb = *(const ulonglong2*)(cbuf + k8 * HRW + 4);
                    unsigned long long w0 = pack2(wq.x);
                    unsigned long long w1 = pack2(wq.y);
                    unsigned long long w2 = pack2(wq.z);
                    unsigned long long w3 = pack2(wq.w);
                    a[0][0] = fma2(ca.x, w0, a[0][0]); a[0][1] = fma2(ca.y, w0, a[0][1]);
                    a[0][2] = fma2(cb.x, w0, a[0][2]); a[0][3] = fma2(cb.y, w0, a[0][3]);
                    a[1][0] = fma2(ca.x, w1, a[1][0]); a[1][1] = fma2(ca.y, w1, a[1][1]);
                    a[1][2] = fma2(cb.x, w1, a[1][2]); a[1][3] = fma2(cb.y, w1, a[1][3]);
                    a[2][0] = fma2(ca.x, w2, a[2][0]); a[2][1] = fma2(ca.y, w2, a[2][1]);
                    a[2][2] = fma2(cb.x, w2, a[2][2]); a[2][3] = fma2(cb.y, w2, a[2][3]);
                    a[3][0] = fma2(ca.x, w3, a[3][0]); a[3][1] = fma2(ca.y, w3, a[3][1]);
                    a[3][2] = fma2(cb.x, w3, a[3][2]); a[3][3] = fma2(cb.y, w3, a[3][3]);
                }
                __syncwarp();
            }
        }

        // ---- write partials: sg[wid][c][b], col c = cq + 8j ----
        #pragma unroll
        for (int j = 0; j < 4; ++j) {
            int c = cq + 8 * j;
            float* dst = sg + (size_t)(wid * NCC + c) * SGR + b0;
            *(ulonglong2*)(dst)     = make_ulonglong2(a[j][0], a[j][1]);
            *(ulonglong2*)(dst + 4) = make_ulonglong2(a[j][2], a[j][3]);
        }
        __syncthreads();

        // ---- stage 1: sum 16 k-partials (512 threads, 2 floats each) ----
        {
            float2 s = make_float2(0.f, 0.f);
            #pragma unroll
            for (int w = 0; w < NW; ++w) {
                float2 v = *(const float2*)(sg + (size_t)(w * NCC + rc) * SGR + rb);
                s.x += v.x; s.y += v.y;
            }
            *(float2*)(sg2 + rc * SG2R + rb) = s;
        }
        __syncthreads();

        // ---- stage 2 pointwise (tid < 256): gates + state update ----
        if (tid < 256) {
            float iv = xz0 + sg2[(0 * 8 + pj) * SG2R + pb];
            float fv = xz1 + sg2[(1 * 8 + pj) * SG2R + pb];
            float gv = xz2 + sg2[(2 * 8 + pj) * SG2R + pb];
            float ov = xz3 + sg2[(3 * 8 + pj) * SG2R + pb];
            creg = sigmoidf_(fv) * creg + sigmoidf_(iv) * tanhf(gv);
            float hval = sigmoidf_(ov) * tanhf(creg);
            g_hsT[((size_t)t * UU + u0 + pj) * BB + bO + pb] = hval;
        }

        // ---- arrive: release h(t) ----
        if (t + 1 < TT) {
            __syncthreads();
            if (tid == 0) st_rel_gpu(&g_flags[bid * FPAD], (unsigned)(t + 1));
        }
    }
}

// ---------------------------------------------------------------------------
__global__ void out_kernel(const float* __restrict__ outW,
                           const float* __restrict__ outb,
                           float* __restrict__ y)
{
    int t  = blockIdx.x;
    int b  = threadIdx.x & 63;
    int ug = threadIdx.x >> 6;   // 0..3
    float s = 0.f;
    const float* base = g_hsT + (size_t)t * UU * BB;
    #pragma unroll 4
    for (int u = ug * 128; u < ug * 128 + 128; ++u)
        s += base[(size_t)u * 64 + b] * outW[u];
    __shared__ float red[4][64];
    red[ug][b] = s;
    __syncthreads();
    if (ug == 0) {
        float v = red[0][b] + red[1][b] + red[2][b] + red[3][b];
        v = g_coef[t] * v + g_shift[t] * g_sumW + outb[0];
        y[b * TT + t] = 1.f / (1.f + expf(-v));
    }
}

// ---------------------------------------------------------------------------
extern "C" void kernel_launch(void* const* d_in, const int* in_sizes, int n_in,
                              void* d_out, int out_size)
{
    (void)in_sizes; (void)n_in; (void)out_size;
    const float* inputs = (const float*)d_in[0];
    const float* kernel = (const float*)d_in[1];
    const float* rec    = (const float*)d_in[2];
    const float* bias   = (const float*)d_in[3];
    const float* attW   = (const float*)d_in[4];
    const float* attb   = (const float*)d_in[5];
    const float* outW   = (const float*)d_in[6];
    const float* outb   = (const float*)d_in[7];
    float* y = (float*)d_out;

    static int smem_set = 0;
    size_t smem_bytes = SMEM_FLOATS * sizeof(float);   // ~168 KB
    if (!smem_set) {
        cudaFuncSetAttribute(lstm_persist,
                             cudaFuncAttributeMaxDynamicSharedMemorySize,
                             (int)smem_bytes);
        smem_set = 1;
    }

    pad_kernel<<<1, 32>>>();                           // keep persist at ncu slot 5
    prep_kernel<<<TT + 1, 256>>>(attW, attb, outW);    // also resets flags
    xz_kernel<<<dim3(GG / 256, TT), 256>>>(inputs, kernel, bias);
    lstm_persist<<<NBLK, NTHR, smem_bytes>>>(rec);
    out_kernel<<<TT, 256>>>(outW, outb, y);
}

// round 17
// speedup vs baseline: 1.6020x; 1.0846x over previous
#include <cuda_runtime.h>
#include <math.h>

#define BB 64
#define TT 256
#define FF 64
#define UU 512
#define GG 2048      // 4*UU
#define NBLK 128
#define NTHR 512
#define CUU 8        // units per block
#define NCC 32       // gate-columns per block (4 gates x 8 units)
#define BBH 32       // batches per block
#define NW 16        // warps (k split 16 ways)
#define KW 32        // k per warp
#define K8 8         // k per cp.async group
#define NG 4         // groups per warp
#define HRW 36       // staged h row stride (floats, 16B-aligned)
#define SGR 36       // sg row stride (floats, 16B-aligned)
#define FPAD 32      // flag padding (128B line each)

// ---- static device scratch (no cudaMalloc anywhere) ----
__device__ __align__(256) float g_hsT[(size_t)TT * UU * BB]; // h: [(t*512+u)*64+b]
__device__ __align__(256) float g_xzT[(size_t)TT * GG * BB]; // xz+bias: [t][g][b]
__device__ float g_coef[TT];
__device__ float g_shift[TT];
__device__ float g_sumW;
__device__ unsigned g_flags[NBLK * FPAD];     // per-block step flags, reset by prep

__device__ __forceinline__ float sigmoidf_(float x) { return 1.f / (1.f + expf(-x)); }

// packed fp32x2 FMA (Blackwell)
__device__ __forceinline__ unsigned long long fma2(unsigned long long a,
                                                   unsigned long long b,
                                                   unsigned long long c) {
    unsigned long long d;
    asm("fma.rn.f32x2 %0, %1, %2, %3;" : "=l"(d) : "l"(a), "l"(b), "l"(c));
    return d;
}
__device__ __forceinline__ unsigned long long pack2(float v) {
    unsigned long long p;
    unsigned u = __float_as_uint(v);
    asm("mov.b64 %0, {%1, %1};" : "=l"(p) : "r"(u));
    return p;
}
__device__ __forceinline__ unsigned ld_acq_gpu(const unsigned* p) {
    unsigned v;
    asm volatile("ld.acquire.gpu.global.u32 %0, [%1];" : "=r"(v) : "l"(p) : "memory");
    return v;
}
__device__ __forceinline__ void st_rel_gpu(unsigned* p, unsigned v) {
    asm volatile("st.release.gpu.global.u32 [%0], %1;" :: "l"(p), "r"(v) : "memory");
}
__device__ __forceinline__ void cp_async16(float* smem_dst, const void* gmem_src) {
    unsigned s = (unsigned)__cvta_generic_to_shared(smem_dst);
    asm volatile("cp.async.cg.shared.global [%0], [%1], 16;\n" :: "r"(s), "l"(gmem_src));
}
#define CP_COMMIT() asm volatile("cp.async.commit_group;" ::: "memory")
#define CP_WAIT_1() asm volatile("cp.async.wait_group 1;" ::: "memory")
#define CP_WAIT_0() asm volatile("cp.async.wait_group 0;" ::: "memory")

// one no-op pad so ncu's capture slot still lands on lstm_persist
__global__ void pad_kernel() {}

// ---------------------------------------------------------------------------
__global__ void prep_kernel(const float* __restrict__ attW,
                            const float* __restrict__ attb,
                            const float* __restrict__ outW)
{
    __shared__ float red[256];
    int tid = threadIdx.x;
    if (blockIdx.x < TT) {
        int t = blockIdx.x;
        float s = 0.f;
        for (int j = tid; j < t; j += 256) s += attW[t * TT + j];
        red[tid] = s;
        __syncthreads();
        for (int off = 128; off > 0; off >>= 1) {
            if (tid < off) red[tid] += red[tid + off];
            __syncthreads();
        }
        if (tid == 0) {
            g_coef[t]  = (t == 0) ? 1.f : red[0];
            g_shift[t] = (t == 0) ? 0.f : attb[t];
        }
    } else {
        if (tid < NBLK) g_flags[tid * FPAD] = 0u;
        red[tid] = outW[tid] + outW[tid + 256];
        __syncthreads();
        for (int off = 128; off > 0; off >>= 1) {
            if (tid < off) red[tid] += red[tid + off];
            __syncthreads();
        }
        if (tid == 0) g_sumW = red[0];
    }
}

// ---------------------------------------------------------------------------
// xz precompute: xzT[t][g][b] = bias[g] + sum_f x[b][t][f] * Wk[f][g]
// ---------------------------------------------------------------------------
__global__ void xz_kernel(const float* __restrict__ x,
                          const float* __restrict__ Wk,
                          const float* __restrict__ bias)
{
    __shared__ float sx[64 * 65];
    __shared__ float sout[256 * 17];

    const int t   = blockIdx.y;
    const int g0  = blockIdx.x * 256;
    const int tid = threadIdx.x;
    const int g   = g0 + tid;

    for (int i = tid; i < 64 * 16; i += 256) {
        int b  = i >> 4;
        int f4 = (i & 15) << 2;
        float4 v = *(const float4*)(x + ((size_t)b * TT + t) * FF + f4);
        sx[b * 65 + f4 + 0] = v.x;
        sx[b * 65 + f4 + 1] = v.y;
        sx[b * 65 + f4 + 2] = v.z;
        sx[b * 65 + f4 + 3] = v.w;
    }

    float wreg[64];
    #pragma unroll 16
    for (int f = 0; f < 64; ++f) wreg[f] = Wk[(size_t)f * GG + g];
    const float bv = bias[g];
    __syncthreads();

    for (int bc = 0; bc < 4; ++bc) {
        float acc[16];
        #pragma unroll
        for (int bb = 0; bb < 16; ++bb) acc[bb] = bv;
        #pragma unroll 8
        for (int f = 0; f < 64; ++f) {
            float w = wreg[f];
            const float* sxb = sx + (bc * 16) * 65 + f;
            #pragma unroll
            for (int bb = 0; bb < 16; ++bb)
                acc[bb] += sxb[bb * 65] * w;
        }
        __syncthreads();
        #pragma unroll
        for (int bb = 0; bb < 16; ++bb) sout[tid * 17 + bb] = acc[bb];
        __syncthreads();
        #pragma unroll
        for (int r = 0; r < 4; ++r) {
            int idx = r * 256 + tid;
            int gg = idx >> 2, s4 = (idx & 3) << 2;
            float4 v = make_float4(sout[gg * 17 + s4 + 0], sout[gg * 17 + s4 + 1],
                                   sout[gg * 17 + s4 + 2], sout[gg * 17 + s4 + 3]);
            *(float4*)(g_xzT + ((size_t)t * GG + g0 + gg) * BB + bc * 16 + s4) = v;
        }
    }
}

// ---------------------------------------------------------------------------
// Persistent LSTM (R16 tiling) + fused reduction/pointwise + half-domain
// flag polling + early release.
// 128 blocks = 64 unit-groups (8 units) x 2 batch-halves (32 batches).
// 512 threads, 16 warps, k split 16x; thread: 4 cols x 8 batches.
// Pointwise thread (pj, pb) sums its 64 scalar partials directly (conflict-
// free: pb varies across lanes) -> no stage-1, no sg2, one less sync.
// Flags: tid<64 poll only own batch-half's 64 producer flags.
// Release: bar.sync among 256 pointwise threads, then tid0 st.release.
// ---------------------------------------------------------------------------
// smem (floats):
//   w4  [512][32]      = 16384 (64 KB)
//   sg  [16][32][36]   = 18432 (72 KB)
//   hst [16][2][8][36] =  9216 (36 KB)
#define OFF_W4   0
#define OFF_SG   (UU * NCC)
#define OFF_HST  (OFF_SG + NW * NCC * SGR)
#define SMEM_FLOATS (OFF_HST + NW * 2 * K8 * HRW)

__global__ void __launch_bounds__(NTHR, 1)
lstm_persist(const float* __restrict__ Rk)    // (U,4U)
{
    extern __shared__ float smem[];
    float* w4  = smem + OFF_W4;
    float* sg  = smem + OFF_SG;
    float* hst = smem + OFF_HST;

    const int tid  = threadIdx.x;
    const int bid  = blockIdx.x;
    const int u0   = (bid >> 1) * CUU;      // unit group
    const int half = bid & 1;               // batch half
    const int bO   = half * BBH;            // batch half offset

    // ---- one-time weight staging: w4[k][m], slot m = cq*4+j <-> col cq+8j ----
    for (int idx = tid; idx < UU * NCC; idx += NTHR) {
        int k = idx >> 5, m = idx & 31;
        int c = (m >> 2) + ((m & 3) << 3);           // col for slot m
        int gcol = (c >> 3) * UU + u0 + (c & 7);
        w4[k * 32 + m] = Rk[(size_t)k * GG + gcol];
    }

    // GEMM identity
    const int wid  = tid >> 5;        // warp 0..15 -> k range [wid*32, ..)
    const int lane = tid & 31;
    const int cq   = lane >> 2;       // 0..7: cols {cq, cq+8, cq+16, cq+24}
    const int bo   = lane & 3;        // 0..3: batches [8bo, 8bo+8) of this half
    const int kb   = wid * KW;
    const int b0   = bo * 8;

    float* slab = hst + (size_t)wid * (2 * K8 * HRW);

    // pointwise identity (tid < 256): unit pj (0..7), batch pb (0..31)
    const int pj = (tid >> 5) & 7;
    const int pb = tid & 31;
    float creg = 0.f;

    // xz pointers (bias folded in)
    const float* xp0 = g_xzT + ((size_t)(0 * UU + u0 + pj)) * BB + bO + pb;
    const float* xp1 = g_xzT + ((size_t)(1 * UU + u0 + pj)) * BB + bO + pb;
    const float* xp2 = g_xzT + ((size_t)(2 * UU + u0 + pj)) * BB + bO + pb;
    const float* xp3 = g_xzT + ((size_t)(3 * UU + u0 + pj)) * BB + bO + pb;

    const float4* wp = (const float4*)w4 + (size_t)kb * 8;   // [k][8 quads]

    // flag this thread polls: producers are the 64 blocks of own half
    const unsigned* pollf = (tid < 64) ? &g_flags[((tid << 1) | half) * FPAD]
                                       : &g_flags[0];

    __syncthreads();

    for (int t = 0; t < TT; ++t) {
        // ---- prefetch this step's xz ----
        float xz0 = __ldg(xp0), xz1 = __ldg(xp1);
        float xz2 = __ldg(xp2), xz3 = __ldg(xp3);
        xp0 += (size_t)GG * BB; xp1 += (size_t)GG * BB;
        xp2 += (size_t)GG * BB; xp3 += (size_t)GG * BB;

        // accumulators: [col j][batch pair p]
        unsigned long long a[4][4];
        #pragma unroll
        for (int j = 0; j < 4; ++j)
            #pragma unroll
            for (int p = 0; p < 4; ++p) a[j][p] = 0ull;

        if (t > 0) {
            // ---- wait: the 64 producer blocks of own half must reach t ----
            if (tid < 64) {
                while (ld_acq_gpu(pollf) < (unsigned)t) { }
            }
            __syncthreads();

            // h slice base: this warp's k rows, this block's batch half
            const float* hsrc = g_hsT + ((size_t)(t - 1) * UU + kb) * BB + bO;

            // group 0: 64 chunks = 2 rounds x 32 lanes
            #pragma unroll
            for (int r = 0; r < 2; ++r) {
                int flat = r * 32 + lane;
                int k8   = flat >> 3;
                int c16  = (flat & 7) << 2;
                cp_async16(slab + k8 * HRW + c16, hsrc + (size_t)k8 * BB + c16);
            }
            CP_COMMIT();

            // ---- 4 groups of 8 k, cp.async pipelined ----
            #pragma unroll
            for (int g = 0; g < NG; ++g) {
                if (g + 1 < NG) {
                    float* dbuf = slab + ((g + 1) & 1) * (K8 * HRW);
                    const float* src = hsrc + (size_t)((g + 1) * K8) * BB;
                    #pragma unroll
                    for (int r = 0; r < 2; ++r) {
                        int flat = r * 32 + lane;
                        int k8   = flat >> 3;
                        int c16  = (flat & 7) << 2;
                        cp_async16(dbuf + k8 * HRW + c16, src + (size_t)k8 * BB + c16);
                    }
                    CP_COMMIT();
                    CP_WAIT_1();
                } else {
                    CP_WAIT_0();
                }
                __syncwarp();

                const float* cbuf = slab + (g & 1) * (K8 * HRW) + b0;
                #pragma unroll
                for (int k8 = 0; k8 < K8; ++k8) {
                    float4 wq = wp[(size_t)(g * K8 + k8) * 8 + cq];
                    ulonglong2 ca = *(const ulonglong2*)(cbuf + k8 * HRW);
                    ulonglong2 cb = *(const ulonglong2*)(cbuf + k8 * HRW + 4);
                    unsigned long long w0 = pack2(wq.x);
                    unsigned long long w1 = pack2(wq.y);
                    unsigned long long w2 = pack2(wq.z);
                    unsigned long long w3 = pack2(wq.w);
                    a[0][0] = fma2(ca.x, w0, a[0][0]); a[0][1] = fma2(ca.y, w0, a[0][1]);
                    a[0][2] = fma2(cb.x, w0, a[0][2]); a[0][3] = fma2(cb.y, w0, a[0][3]);
                    a[1][0] = fma2(ca.x, w1, a[1][0]); a[1][1] = fma2(ca.y, w1, a[1][1]);
                    a[1][2] = fma2(cb.x, w1, a[1][2]); a[1][3] = fma2(cb.y, w1, a[1][3]);
                    a[2][0] = fma2(ca.x, w2, a[2][0]); a[2][1] = fma2(ca.y, w2, a[2][1]);
                    a[2][2] = fma2(cb.x, w2, a[2][2]); a[2][3] = fma2(cb.y, w2, a[2][3]);
                    a[3][0] = fma2(ca.x, w3, a[3][0]); a[3][1] = fma2(ca.y, w3, a[3][1]);
                    a[3][2] = fma2(cb.x, w3, a[3][2]); a[3][3] = fma2(cb.y, w3, a[3][3]);
                }
                __syncwarp();
            }
        }

        // ---- write partials: sg[wid][c][b], col c = cq + 8j ----
        #pragma unroll
        for (int j = 0; j < 4; ++j) {
            int c = cq + 8 * j;
            float* dst = sg + (size_t)(wid * NCC + c) * SGR + b0;
            *(ulonglong2*)(dst)     = make_ulonglong2(a[j][0], a[j][1]);
            *(ulonglong2*)(dst + 4) = make_ulonglong2(a[j][2], a[j][3]);
        }
        __syncthreads();

        // ---- fused reduction + pointwise (tid < 256) ----
        if (tid < 256) {
            float gsum[4];
            #pragma unroll
            for (int g4 = 0; g4 < 4; ++g4) {
                float s = 0.f;
                #pragma unroll
                for (int w = 0; w < NW; ++w)
                    s += sg[(size_t)(w * NCC + g4 * 8 + pj) * SGR + pb];
                gsum[g4] = s;
            }
            float iv = xz0 + gsum[0];
            float fv = xz1 + gsum[1];
            float gv = xz2 + gsum[2];
            float ov = xz3 + gsum[3];
            creg = sigmoidf_(fv) * creg + sigmoidf_(iv) * tanhf(gv);
            float hval = sigmoidf_(ov) * tanhf(creg);
            g_hsT[((size_t)t * UU + u0 + pj) * BB + bO + pb] = hval;

            // ---- early release: only pointwise warps gate the flag ----
            if (t + 1 < TT) {
                asm volatile("bar.sync 1, 256;" ::: "memory");
                if (tid == 0) st_rel_gpu(&g_flags[bid * FPAD], (unsigned)(t + 1));
            }
        }
    }
}

// ---------------------------------------------------------------------------
__global__ void out_kernel(const float* __restrict__ outW,
                           const float* __restrict__ outb,
                           float* __restrict__ y)
{
    int t  = blockIdx.x;
    int b  = threadIdx.x & 63;
    int ug = threadIdx.x >> 6;   // 0..3
    float s = 0.f;
    const float* base = g_hsT + (size_t)t * UU * BB;
    #pragma unroll 4
    for (int u = ug * 128; u < ug * 128 + 128; ++u)
        s += base[(size_t)u * 64 + b] * outW[u];
    __shared__ float red[4][64];
    red[ug][b] = s;
    __syncthreads();
    if (ug == 0) {
        float v = red[0][b] + red[1][b] + red[2][b] + red[3][b];
        v = g_coef[t] * v + g_shift[t] * g_sumW + outb[0];
        y[b * TT + t] = 1.f / (1.f + expf(-v));
    }
}

// ---------------------------------------------------------------------------
extern "C" void kernel_launch(void* const* d_in, const int* in_sizes, int n_in,
                              void* d_out, int out_size)
{
    (void)in_sizes; (void)n_in; (void)out_size;
    const float* inputs = (const float*)d_in[0];
    const float* kernel = (const float*)d_in[1];
    const float* rec    = (const float*)d_in[2];
    const float* bias   = (const float*)d_in[3];
    const float* attW   = (const float*)d_in[4];
    const float* attb   = (const float*)d_in[5];
    const float* outW   = (const float*)d_in[6];
    const float* outb   = (const float*)d_in[7];
    float* y = (float*)d_out;

    static int smem_set = 0;
    size_t smem_bytes = SMEM_FLOATS * sizeof(float);   // ~172 KB
    if (!smem_set) {
        cudaFuncSetAttribute(lstm_persist,
                             cudaFuncAttributeMaxDynamicSharedMemorySize,
                             (int)smem_bytes);
        smem_set = 1;
    }

    pad_kernel<<<1, 32>>>();                           // keep persist at ncu slot 5
    prep_kernel<<<TT + 1, 256>>>(attW, attb, outW);    // also resets flags
    xz_kernel<<<dim3(GG / 256, TT), 256>>>(inputs, kernel, bias);
    lstm_persist<<<NBLK, NTHR, smem_bytes>>>(rec);
    out_kernel<<<TT, 256>>>(outW, outb, y);
}